// round 1
// baseline (speedup 1.0000x reference)
#include <cuda_runtime.h>
#include <math.h>

#define BATCH 1024
#define HDIM  1024
#define GATES 4096
#define INDIM 768
#define EPSV  1e-8f

// ---------------- scratch (no allocations allowed) ----------------
__device__ float g_h[BATCH * HDIM];
__device__ float g_c[BATCH * HDIM];
__device__ float g_Fx[BATCH * 16 * 64];
__device__ float g_Fy[BATCH * 16 * 64];
__device__ float g_gamma[BATCH];
__device__ float g_r[BATCH * INDIM];
__device__ float g_gates[BATCH * GATES];
__device__ float g_t[BATCH * HDIM];

// ---------------- zero init h, c ----------------
__global__ void zero_hc() {
    int i = blockIdx.x * blockDim.x + threadIdx.x;
    g_h[i] = 0.f;
    g_c[i] = 0.f;
}

// ---------------- attention params + filterbank ----------------
// One block per batch element. p = h @ W_att^T + b_att, then Fx/Fy (16x64 each, row-normalized).
__global__ __launch_bounds__(256) void att_filterbank(
    const float* __restrict__ W_att, const float* __restrict__ b_att)
{
    int b = blockIdx.x;
    int tid = threadIdx.x;
    const float* hrow = g_h + (size_t)b * HDIM;

    float a0 = 0.f, a1 = 0.f, a2 = 0.f, a3 = 0.f, a4 = 0.f;
    for (int k = tid; k < HDIM; k += 256) {
        float hv = hrow[k];
        a0 += hv * W_att[k];
        a1 += hv * W_att[HDIM + k];
        a2 += hv * W_att[2 * HDIM + k];
        a3 += hv * W_att[3 * HDIM + k];
        a4 += hv * W_att[4 * HDIM + k];
    }
    #pragma unroll
    for (int o = 16; o > 0; o >>= 1) {
        a0 += __shfl_down_sync(0xffffffffu, a0, o);
        a1 += __shfl_down_sync(0xffffffffu, a1, o);
        a2 += __shfl_down_sync(0xffffffffu, a2, o);
        a3 += __shfl_down_sync(0xffffffffu, a3, o);
        a4 += __shfl_down_sync(0xffffffffu, a4, o);
    }
    __shared__ float red[8][5];
    int warp = tid >> 5, lane = tid & 31;
    if (lane == 0) {
        red[warp][0] = a0; red[warp][1] = a1; red[warp][2] = a2;
        red[warp][3] = a3; red[warp][4] = a4;
    }
    __syncthreads();
    __shared__ float p[5];
    if (tid < 5) {
        float s = b_att[tid];
        #pragma unroll
        for (int w = 0; w < 8; w++) s += red[w][tid];
        p[tid] = s;
    }
    __syncthreads();

    float gx     = 32.5f * (p[0] + 1.f);            // (A+1)/2 * (gx_+1)
    float gy     = 32.5f * (p[1] + 1.f);
    float inv2s2 = 0.5f * expf(-p[2]);              // 1/(2*sigma2)
    float delta  = (63.f / 15.f) * expf(p[3]);
    float gam    = expf(p[4]);

    __shared__ float fx[16][65];
    __shared__ float fy[16][65];
    for (int idx = tid; idx < 1024; idx += 256) {
        int i = idx >> 6, a = idx & 63;
        float mu = (i - 8.5f) * delta;
        float dx = (float)a - (gx + mu);
        float dy = (float)a - (gy + mu);
        fx[i][a] = expf(-dx * dx * inv2s2);
        fy[i][a] = expf(-dy * dy * inv2s2);
    }
    __syncthreads();
    __shared__ float rs[32];
    if (tid < 32) {
        float s = 0.f;
        if (tid < 16) {
            for (int a = 0; a < 64; a++) s += fx[tid][a];
        } else {
            for (int a = 0; a < 64; a++) s += fy[tid - 16][a];
        }
        rs[tid] = 1.f / (s + EPSV);
    }
    __syncthreads();
    for (int idx = tid; idx < 1024; idx += 256) {
        int i = idx >> 6, a = idx & 63;
        g_Fx[(size_t)b * 1024 + idx] = fx[i][a] * rs[i];
        g_Fy[(size_t)b * 1024 + idx] = fy[i][a] * rs[16 + i];
    }
    if (tid == 0) g_gamma[b] = gam;
}

// ---------------- glimpse: r = gamma * (Fy @ img @ Fx^T) ----------------
// grid (3, 1024): one block per (channel, batch)
__global__ __launch_bounds__(256) void glimpse_kernel(const float* __restrict__ x)
{
    int c = blockIdx.x;
    int b = blockIdx.y;
    int tid = threadIdx.x;

    __shared__ float simg[64][64];   // img[y][a]
    __shared__ float sfy[16][64];
    __shared__ float sfx[16][65];    // padded: avoids stride-64 bank conflicts
    __shared__ float stmp[16][64];

    const float4* img4 = (const float4*)(x + ((size_t)(b * 3 + c)) * 4096);
    float4* simg4 = (float4*)&simg[0][0];
    for (int i = tid; i < 1024; i += 256) simg4[i] = img4[i];

    const float* fyp = g_Fy + (size_t)b * 1024;
    const float* fxp = g_Fx + (size_t)b * 1024;
    float* sfyf = (float*)sfy;
    for (int i = tid; i < 1024; i += 256) {
        sfyf[i] = fyp[i];
        sfx[i >> 6][i & 63] = fxp[i];
    }
    __syncthreads();

    // tmp[n][a] = sum_y Fy[n][y] * img[y][a]
    for (int o = tid; o < 1024; o += 256) {
        int n = o >> 6, a = o & 63;
        float s = 0.f;
        #pragma unroll 8
        for (int y = 0; y < 64; y++) s += sfy[n][y] * simg[y][a];
        stmp[n][a] = s;
    }
    __syncthreads();

    // out[n][x'] = sum_a tmp[n][a] * Fx[x'][a]
    float gam = g_gamma[b];
    int n = tid >> 4, xx = tid & 15;
    float s = 0.f;
    #pragma unroll 8
    for (int a = 0; a < 64; a++) s += stmp[n][a] * sfx[xx][a];
    g_r[(size_t)b * INDIM + c * 256 + tid] = s * gam;
}

// ---------------- tiled SGEMM (NT): C[M,N] = A0@W0^T + A1@W1^T + bias ----------------
// A matrices are (M, K) row-major, W matrices are (N, K) row-major (dot along contiguous K).
// 128x128 block tile, BK=8, 8x8 per thread, double-buffered smem.
__global__ __launch_bounds__(256) void gemm_bias(
    const float* __restrict__ A0, const float* __restrict__ W0, int K0,
    const float* __restrict__ A1, const float* __restrict__ W1, int K1,
    const float* __restrict__ bias0, const float* __restrict__ bias1,
    float* __restrict__ C, int N, int relu)
{
    __shared__ float As[2][8][128];
    __shared__ float Bs[2][8][128];

    int tid = threadIdx.x;
    int bm = blockIdx.y * 128;
    int bn = blockIdx.x * 128;
    int lr = tid >> 1;             // 0..127
    int lc = (tid & 1) << 2;       // 0 or 4
    int nT = (K0 + K1) >> 3;

    float4 av, bv;
    av = *(const float4*)(A0 + (size_t)(bm + lr) * K0 + lc);
    bv = *(const float4*)(W0 + (size_t)(bn + lr) * K0 + lc);

    float acc[8][8];
    #pragma unroll
    for (int i = 0; i < 8; i++)
        #pragma unroll
        for (int j = 0; j < 8; j++) acc[i][j] = 0.f;

    int tm = (tid >> 4) << 3;
    int tn = (tid & 15) << 3;

    for (int kt = 0; kt < nT; kt++) {
        int buf = kt & 1;
        As[buf][lc + 0][lr] = av.x; As[buf][lc + 1][lr] = av.y;
        As[buf][lc + 2][lr] = av.z; As[buf][lc + 3][lr] = av.w;
        Bs[buf][lc + 0][lr] = bv.x; Bs[buf][lc + 1][lr] = bv.y;
        Bs[buf][lc + 2][lr] = bv.z; Bs[buf][lc + 3][lr] = bv.w;
        __syncthreads();

        if (kt + 1 < nT) {
            int kg = (kt + 1) << 3;
            const float* Ap; const float* Wp; int K, kl;
            if (kg < K0) { Ap = A0; Wp = W0; K = K0; kl = kg; }
            else         { Ap = A1; Wp = W1; K = K1; kl = kg - K0; }
            av = *(const float4*)(Ap + (size_t)(bm + lr) * K + kl + lc);
            bv = *(const float4*)(Wp + (size_t)(bn + lr) * K + kl + lc);
        }

        #pragma unroll
        for (int k = 0; k < 8; k++) {
            float a[8], bb[8];
            *(float4*)&a[0]  = *(float4*)&As[buf][k][tm];
            *(float4*)&a[4]  = *(float4*)&As[buf][k][tm + 4];
            *(float4*)&bb[0] = *(float4*)&Bs[buf][k][tn];
            *(float4*)&bb[4] = *(float4*)&Bs[buf][k][tn + 4];
            #pragma unroll
            for (int i = 0; i < 8; i++)
                #pragma unroll
                for (int j = 0; j < 8; j++)
                    acc[i][j] += a[i] * bb[j];
        }
    }

    #pragma unroll
    for (int i = 0; i < 8; i++) {
        int row = bm + tm + i;
        #pragma unroll
        for (int j = 0; j < 8; j++) {
            int col = bn + tn + j;
            float v = acc[i][j] + bias0[col];
            if (bias1) v += bias1[col];
            if (relu) v = fmaxf(v, 0.f);
            C[(size_t)row * N + col] = v;
        }
    }
}

// ---------------- LSTM pointwise ----------------
__global__ void lstm_update() {
    int idx = blockIdx.x * blockDim.x + threadIdx.x;  // 1M threads
    int b = idx >> 10, j = idx & 1023;
    const float* g = g_gates + (size_t)b * GATES + j;
    float ig = g[0], fg = g[1024], gg = g[2048], og = g[3072];
    ig = 1.f / (1.f + expf(-ig));
    fg = 1.f / (1.f + expf(-fg));
    og = 1.f / (1.f + expf(-og));
    gg = tanhf(gg);
    float cn = fg * g_c[idx] + ig * gg;
    g_c[idx] = cn;
    g_h[idx] = og * tanhf(cn);
}

// ---------------- final small FC: out = t @ W_fc^T + b_fc ----------------
__global__ __launch_bounds__(256) void fc_out(
    const float* __restrict__ W, const float* __restrict__ bias, float* __restrict__ out)
{
    int b = blockIdx.x;
    int tid = threadIdx.x;
    const float* trow = g_t + (size_t)b * HDIM;
    float acc[10];
    #pragma unroll
    for (int j = 0; j < 10; j++) acc[j] = 0.f;
    for (int k = tid; k < HDIM; k += 256) {
        float tv = trow[k];
        #pragma unroll
        for (int j = 0; j < 10; j++) acc[j] += tv * W[j * HDIM + k];
    }
    #pragma unroll
    for (int j = 0; j < 10; j++)
        #pragma unroll
        for (int o = 16; o > 0; o >>= 1)
            acc[j] += __shfl_down_sync(0xffffffffu, acc[j], o);
    __shared__ float red[8][10];
    int warp = tid >> 5, lane = tid & 31;
    if (lane == 0)
        #pragma unroll
        for (int j = 0; j < 10; j++) red[warp][j] = acc[j];
    __syncthreads();
    if (tid < 10) {
        float s = bias[tid];
        #pragma unroll
        for (int w = 0; w < 8; w++) s += red[w][tid];
        out[b * 10 + tid] = s;
    }
}

// ---------------- launcher ----------------
extern "C" void kernel_launch(void* const* d_in, const int* in_sizes, int n_in,
                              void* d_out, int out_size)
{
    const float* x      = (const float*)d_in[0];
    const float* W_att  = (const float*)d_in[1];
    const float* b_att  = (const float*)d_in[2];
    const float* W_ih   = (const float*)d_in[3];
    const float* W_hh   = (const float*)d_in[4];
    const float* b_ih   = (const float*)d_in[5];
    const float* b_hh   = (const float*)d_in[6];
    const float* W_fc0  = (const float*)d_in[7];
    const float* b_fc0  = (const float*)d_in[8];
    const float* W_fc   = (const float*)d_in[9];
    const float* b_fc   = (const float*)d_in[10];
    float* out = (float*)d_out;

    // resolve scratch symbol addresses (no allocation, capture-safe)
    void *p_r, *p_h, *p_gates, *p_t;
    cudaGetSymbolAddress(&p_r, g_r);
    cudaGetSymbolAddress(&p_h, g_h);
    cudaGetSymbolAddress(&p_gates, g_gates);
    cudaGetSymbolAddress(&p_t, g_t);
    float* s_r = (float*)p_r;
    float* s_h = (float*)p_h;
    float* s_gates = (float*)p_gates;
    float* s_t = (float*)p_t;

    zero_hc<<<(BATCH * HDIM) / 256, 256>>>();

    for (int t = 0; t < 16; t++) {
        att_filterbank<<<BATCH, 256>>>(W_att, b_att);
        glimpse_kernel<<<dim3(3, BATCH), 256>>>(x);
        gemm_bias<<<dim3(GATES / 128, BATCH / 128), 256>>>(
            s_r, W_ih, INDIM, s_h, W_hh, HDIM, b_ih, b_hh, s_gates, GATES, 0);
        lstm_update<<<(BATCH * HDIM) / 256, 256>>>();
    }

    gemm_bias<<<dim3(HDIM / 128, BATCH / 128), 256>>>(
        s_h, W_fc0, HDIM, nullptr, nullptr, 0, b_fc0, nullptr, s_t, HDIM, 1);
    fc_out<<<BATCH, 256>>>(W_fc, b_fc, out);
}

// round 3
// speedup vs baseline: 1.5332x; 1.5332x over previous
#include <cuda_runtime.h>
#include <cuda_bf16.h>
#include <math.h>
#include <stdint.h>

#define BATCH 1024
#define HDIM  1024
#define GATES 4096
#define INDIM 768
#define KDIM  1792
#define EPSV  1e-8f

// ---------------- scratch (no allocations allowed) ----------------
__device__ float g_h[BATCH * HDIM];
__device__ float g_c[BATCH * HDIM];
__device__ float g_Fx[BATCH * 1024];
__device__ float g_Fy[BATCH * 1024];
__device__ float g_gamma[BATCH];
__device__ float g_t[BATCH * HDIM];
__device__ float g_biasp[GATES];
__device__ float g_gates[(size_t)BATCH * GATES];
__device__ __align__(16) __nv_bfloat16 g_Ah[BATCH * KDIM];
__device__ __align__(16) __nv_bfloat16 g_Al[BATCH * KDIM];
__device__ __align__(16) __nv_bfloat16 g_Wh[(size_t)GATES * KDIM];
__device__ __align__(16) __nv_bfloat16 g_Wl[(size_t)GATES * KDIM];

// ---------------- helpers ----------------
__device__ __forceinline__ uint32_t smem_u32(const void* p) {
    uint32_t a;
    asm("{ .reg .u64 t; cvta.to.shared.u64 t, %1; cvt.u32.u64 %0, t; }" : "=r"(a) : "l"(p));
    return a;
}
static __device__ __forceinline__ void cpa16(uint32_t s, const void* g) {
    asm volatile("cp.async.cg.shared.global [%0], [%1], 16;" :: "r"(s), "l"(g));
}
static __device__ __forceinline__ void ldmx4(uint32_t* r, uint32_t addr) {
    asm volatile("ldmatrix.sync.aligned.m8n8.x4.shared.b16 {%0,%1,%2,%3}, [%4];"
                 : "=r"(r[0]), "=r"(r[1]), "=r"(r[2]), "=r"(r[3]) : "r"(addr));
}
static __device__ __forceinline__ void mma16816(float* d, const uint32_t* a, const uint32_t* b) {
    asm volatile(
        "mma.sync.aligned.m16n8k16.row.col.f32.bf16.bf16.f32 "
        "{%0,%1,%2,%3}, {%4,%5,%6,%7}, {%8,%9}, {%0,%1,%2,%3};"
        : "+f"(d[0]), "+f"(d[1]), "+f"(d[2]), "+f"(d[3])
        : "r"(a[0]), "r"(a[1]), "r"(a[2]), "r"(a[3]), "r"(b[0]), "r"(b[1]));
}

// ---------------- init ----------------
__global__ void zero_state() {
    int idx = blockIdx.x * 256 + threadIdx.x;
    g_h[idx] = 0.f;
    g_c[idx] = 0.f;
    int row = idx >> 10, j = idx & 1023;
    __nv_bfloat16 z = __float2bfloat16(0.f);
    g_Ah[(size_t)row * KDIM + 768 + j] = z;
    g_Al[(size_t)row * KDIM + 768 + j] = z;
}

// ---------------- weight convert: bf16 split (no permutation) ----------------
__global__ __launch_bounds__(256) void convert_weights(
    const float* __restrict__ W_ih, const float* __restrict__ W_hh,
    const float* __restrict__ b_ih, const float* __restrict__ b_hh)
{
    int r = blockIdx.x;                     // 0..4095
    for (int c = threadIdx.x; c < KDIM; c += 256) {
        float w = (c < 768) ? W_ih[(size_t)r * 768 + c]
                            : W_hh[(size_t)r * 1024 + (c - 768)];
        __nv_bfloat16 wh = __float2bfloat16(w);
        g_Wh[(size_t)r * KDIM + c] = wh;
        g_Wl[(size_t)r * KDIM + c] = __float2bfloat16(w - __bfloat162float(wh));
    }
    if (threadIdx.x == 0) g_biasp[r] = b_ih[r] + b_hh[r];
}

// ---------------- attention params + filterbank ----------------
__global__ __launch_bounds__(256) void att_filterbank(
    const float* __restrict__ W_att, const float* __restrict__ b_att)
{
    int b = blockIdx.x;
    int tid = threadIdx.x;
    const float* hrow = g_h + (size_t)b * HDIM;

    float a0 = 0.f, a1 = 0.f, a2 = 0.f, a3 = 0.f, a4 = 0.f;
    for (int k = tid; k < HDIM; k += 256) {
        float hv = hrow[k];
        a0 += hv * W_att[k];
        a1 += hv * W_att[HDIM + k];
        a2 += hv * W_att[2 * HDIM + k];
        a3 += hv * W_att[3 * HDIM + k];
        a4 += hv * W_att[4 * HDIM + k];
    }
    #pragma unroll
    for (int o = 16; o > 0; o >>= 1) {
        a0 += __shfl_down_sync(0xffffffffu, a0, o);
        a1 += __shfl_down_sync(0xffffffffu, a1, o);
        a2 += __shfl_down_sync(0xffffffffu, a2, o);
        a3 += __shfl_down_sync(0xffffffffu, a3, o);
        a4 += __shfl_down_sync(0xffffffffu, a4, o);
    }
    __shared__ float red[8][5];
    int warp = tid >> 5, lane = tid & 31;
    if (lane == 0) {
        red[warp][0] = a0; red[warp][1] = a1; red[warp][2] = a2;
        red[warp][3] = a3; red[warp][4] = a4;
    }
    __syncthreads();
    __shared__ float p[5];
    if (tid < 5) {
        float s = b_att[tid];
        #pragma unroll
        for (int w = 0; w < 8; w++) s += red[w][tid];
        p[tid] = s;
    }
    __syncthreads();

    float gx     = 32.5f * (p[0] + 1.f);
    float gy     = 32.5f * (p[1] + 1.f);
    float inv2s2 = 0.5f * expf(-p[2]);
    float delta  = (63.f / 15.f) * expf(p[3]);
    float gam    = expf(p[4]);

    __shared__ float fx[16][65];
    __shared__ float fy[16][65];
    for (int idx = tid; idx < 1024; idx += 256) {
        int i = idx >> 6, a = idx & 63;
        float mu = (i - 8.5f) * delta;
        float dx = (float)a - (gx + mu);
        float dy = (float)a - (gy + mu);
        fx[i][a] = __expf(-dx * dx * inv2s2);
        fy[i][a] = __expf(-dy * dy * inv2s2);
    }
    __syncthreads();
    __shared__ float rs[32];
    if (tid < 32) {
        float s = 0.f;
        if (tid < 16) {
            for (int a = 0; a < 64; a++) s += fx[tid][a];
        } else {
            for (int a = 0; a < 64; a++) s += fy[tid - 16][a];
        }
        rs[tid] = 1.f / (s + EPSV);
    }
    __syncthreads();
    for (int idx = tid; idx < 1024; idx += 256) {
        int i = idx >> 6, a = idx & 63;
        g_Fx[(size_t)b * 1024 + idx] = fx[i][a] * rs[i];
        g_Fy[(size_t)b * 1024 + idx] = fy[i][a] * rs[16 + i];
    }
    if (tid == 0) g_gamma[b] = gam;
}

// ---------------- glimpse: writes split-bf16 r directly into A ----------------
__global__ __launch_bounds__(256) void glimpse_kernel(const float* __restrict__ x)
{
    int c = blockIdx.x;
    int b = blockIdx.y;
    int tid = threadIdx.x;

    __shared__ float simg[64][64];
    __shared__ float sfy[16][64];
    __shared__ float sfx[16][65];
    __shared__ float stmp[16][64];

    const float4* img4 = (const float4*)(x + ((size_t)(b * 3 + c)) * 4096);
    float4* simg4 = (float4*)&simg[0][0];
    for (int i = tid; i < 1024; i += 256) simg4[i] = img4[i];

    const float* fyp = g_Fy + (size_t)b * 1024;
    const float* fxp = g_Fx + (size_t)b * 1024;
    float* sfyf = (float*)sfy;
    for (int i = tid; i < 1024; i += 256) {
        sfyf[i] = fyp[i];
        sfx[i >> 6][i & 63] = fxp[i];
    }
    __syncthreads();

    for (int o = tid; o < 1024; o += 256) {
        int n = o >> 6, a = o & 63;
        float s = 0.f;
        #pragma unroll 8
        for (int y = 0; y < 64; y++) s += sfy[n][y] * simg[y][a];
        stmp[n][a] = s;
    }
    __syncthreads();

    float gam = g_gamma[b];
    int n = tid >> 4, xx = tid & 15;
    float s = 0.f;
    #pragma unroll 8
    for (int a = 0; a < 64; a++) s += stmp[n][a] * sfx[xx][a];
    float v = s * gam;
    __nv_bfloat16 vh = __float2bfloat16(v);
    size_t off = (size_t)b * KDIM + c * 256 + tid;
    g_Ah[off] = vh;
    g_Al[off] = __float2bfloat16(v - __bfloat162float(vh));
}

// ---------------- gates GEMM: mma.sync bf16 split-3 ----------------
// C[1024,4096] = A[1024,1792] @ W^T[4096,1792]
// CTA tile 128x128, 8 warps (2x4), warp tile 64x32, BK=32, cp.async double buffer.
#define TSZ   10240              // one tile: 128 rows * 80B
#define BUFSZ (4 * TSZ)          // AH, AL, BH, BL
#define GSMEM (2 * BUFSZ)        // 81920 B
#define NKB2  56                 // 1792 / 32

__global__ __launch_bounds__(256, 2) void gemm_gates()
{
    extern __shared__ char smem[];
    const int tid = threadIdx.x;
    const int lane = tid & 31;
    const int wid = tid >> 5;
    const int wm = wid >> 2;          // 0..1
    const int wn = wid & 3;           // 0..3
    const int bn = blockIdx.x * 128;
    const int bm = blockIdx.y * 128;

    float acc[4][4][4];
    #pragma unroll
    for (int i = 0; i < 4; i++)
        #pragma unroll
        for (int j = 0; j < 4; j++)
            #pragma unroll
            for (int q = 0; q < 4; q++) acc[i][j][q] = 0.f;

    // per-thread cp.async source row/chunk (same for all 4 tiles)
    // cid = tid + i*256 ; tile = cid>>9 ; w = cid&511 ; row=w>>2 ; ch=w&3
    // ldmatrix base offsets
    const uint32_t a_off = (uint32_t)((wm * 64 + (lane & 15)) * 80 + (lane >> 4) * 16);
    const uint32_t b_row = (uint32_t)(wn * 32 + (lane & 7) + ((lane >> 4) << 3));
    const uint32_t b_off = b_row * 80 + (((uint32_t)lane >> 3) & 1) * 16;

    // ---- issue helper (macro-free inline) ----
    auto issue = [&](int kb, char* buf) {
        int kcol = kb * 32;
        #pragma unroll
        for (int i = 0; i < 8; i++) {
            int cid = tid + i * 256;
            int t4 = cid >> 9;
            int w = cid & 511;
            int row = w >> 2, ch = w & 3;
            const __nv_bfloat16* gp;
            if (t4 == 0)      gp = g_Ah + (size_t)(bm + row) * KDIM + kcol + ch * 8;
            else if (t4 == 1) gp = g_Al + (size_t)(bm + row) * KDIM + kcol + ch * 8;
            else if (t4 == 2) gp = g_Wh + (size_t)(bn + row) * KDIM + kcol + ch * 8;
            else              gp = g_Wl + (size_t)(bn + row) * KDIM + kcol + ch * 8;
            cpa16(smem_u32(buf + t4 * TSZ + row * 80 + ch * 16), gp);
        }
    };

    issue(0, smem);
    asm volatile("cp.async.commit_group;" ::: "memory");

    for (int kb = 0; kb < NKB2; kb++) {
        if (kb + 1 < NKB2) issue(kb + 1, smem + ((kb + 1) & 1) * BUFSZ);
        asm volatile("cp.async.commit_group;" ::: "memory");
        asm volatile("cp.async.wait_group 1;" ::: "memory");
        __syncthreads();

        char* buf = smem + (kb & 1) * BUFSZ;
        uint32_t sb = smem_u32(buf);

        #pragma unroll
        for (int kh = 0; kh < 2; kh++) {
            uint32_t kadd = kh * 32;
            uint32_t aH[4][4], aL[4][4], bH[2][4], bL[2][4];
            #pragma unroll
            for (int mt = 0; mt < 4; mt++)
                ldmx4(aH[mt], sb + 0 * TSZ + a_off + mt * (16 * 80) + kadd);
            #pragma unroll
            for (int g = 0; g < 2; g++)
                ldmx4(bH[g], sb + 2 * TSZ + b_off + g * (16 * 80) + kadd);
            #pragma unroll
            for (int g = 0; g < 2; g++)
                ldmx4(bL[g], sb + 3 * TSZ + b_off + g * (16 * 80) + kadd);

            // hi * hi
            #pragma unroll
            for (int mt = 0; mt < 4; mt++)
                #pragma unroll
                for (int nt = 0; nt < 4; nt++)
                    mma16816(acc[mt][nt], aH[mt], &bH[nt >> 1][(nt & 1) * 2]);
            // hi * lo
            #pragma unroll
            for (int mt = 0; mt < 4; mt++)
                #pragma unroll
                for (int nt = 0; nt < 4; nt++)
                    mma16816(acc[mt][nt], aH[mt], &bL[nt >> 1][(nt & 1) * 2]);
            // lo * hi
            #pragma unroll
            for (int mt = 0; mt < 4; mt++)
                ldmx4(aL[mt], sb + 1 * TSZ + a_off + mt * (16 * 80) + kadd);
            #pragma unroll
            for (int mt = 0; mt < 4; mt++)
                #pragma unroll
                for (int nt = 0; nt < 4; nt++)
                    mma16816(acc[mt][nt], aL[mt], &bH[nt >> 1][(nt & 1) * 2]);
        }
        __syncthreads();
    }

    // epilogue: raw gate pre-activations (bias added in lstm_update)
    #pragma unroll
    for (int mt = 0; mt < 4; mt++) {
        int r0 = bm + wm * 64 + mt * 16 + (lane >> 2);
        #pragma unroll
        for (int nt = 0; nt < 4; nt++) {
            int c0 = bn + wn * 32 + nt * 8 + (lane & 3) * 2;
            *(float2*)&g_gates[(size_t)r0 * GATES + c0] =
                make_float2(acc[mt][nt][0], acc[mt][nt][1]);
            *(float2*)&g_gates[(size_t)(r0 + 8) * GATES + c0] =
                make_float2(acc[mt][nt][2], acc[mt][nt][3]);
        }
    }
}

// ---------------- LSTM pointwise (+ split-bf16 h into A) ----------------
__global__ void lstm_update() {
    int idx = blockIdx.x * 256 + threadIdx.x;
    int b = idx >> 10, j = idx & 1023;
    const float* g = g_gates + (size_t)b * GATES;
    float vi = g[j]        + g_biasp[j];
    float vf = g[1024 + j] + g_biasp[1024 + j];
    float vg = g[2048 + j] + g_biasp[2048 + j];
    float vo = g[3072 + j] + g_biasp[3072 + j];
    float ig = 1.f / (1.f + __expf(-vi));
    float fg = 1.f / (1.f + __expf(-vf));
    float og = 1.f / (1.f + __expf(-vo));
    float gg = 2.f / (1.f + __expf(-2.f * vg)) - 1.f;
    float cn = fg * g_c[idx] + ig * gg;
    g_c[idx] = cn;
    float hn = og * (2.f / (1.f + __expf(-2.f * cn)) - 1.f);
    g_h[idx] = hn;
    __nv_bfloat16 hh = __float2bfloat16(hn);
    size_t off = (size_t)b * KDIM + 768 + j;
    g_Ah[off] = hh;
    g_Al[off] = __float2bfloat16(hn - __bfloat162float(hh));
}

// ---------------- fp32 SGEMM for fc0 ----------------
__global__ __launch_bounds__(256) void gemm_bias(
    const float* __restrict__ A0, const float* __restrict__ W0, int K0,
    const float* __restrict__ bias0, float* __restrict__ C, int N, int relu)
{
    __shared__ float As[2][8][128];
    __shared__ float Bs[2][8][128];

    int tid = threadIdx.x;
    int bm = blockIdx.y * 128;
    int bn = blockIdx.x * 128;
    int lr = tid >> 1;
    int lc = (tid & 1) << 2;
    int nT = K0 >> 3;

    float4 av, bv;
    av = *(const float4*)(A0 + (size_t)(bm + lr) * K0 + lc);
    bv = *(const float4*)(W0 + (size_t)(bn + lr) * K0 + lc);

    float acc[8][8];
    #pragma unroll
    for (int i = 0; i < 8; i++)
        #pragma unroll
        for (int j = 0; j < 8; j++) acc[i][j] = 0.f;

    int tm = (tid >> 4) << 3;
    int tn = (tid & 15) << 3;

    for (int kt = 0; kt < nT; kt++) {
        int buf = kt & 1;
        As[buf][lc + 0][lr] = av.x; As[buf][lc + 1][lr] = av.y;
        As[buf][lc + 2][lr] = av.z; As[buf][lc + 3][lr] = av.w;
        Bs[buf][lc + 0][lr] = bv.x; Bs[buf][lc + 1][lr] = bv.y;
        Bs[buf][lc + 2][lr] = bv.z; Bs[buf][lc + 3][lr] = bv.w;
        __syncthreads();

        if (kt + 1 < nT) {
            int kg = (kt + 1) << 3;
            av = *(const float4*)(A0 + (size_t)(bm + lr) * K0 + kg + lc);
            bv = *(const float4*)(W0 + (size_t)(bn + lr) * K0 + kg + lc);
        }

        #pragma unroll
        for (int k = 0; k < 8; k++) {
            float a[8], bb[8];
            *(float4*)&a[0]  = *(float4*)&As[buf][k][tm];
            *(float4*)&a[4]  = *(float4*)&As[buf][k][tm + 4];
            *(float4*)&bb[0] = *(float4*)&Bs[buf][k][tn];
            *(float4*)&bb[4] = *(float4*)&Bs[buf][k][tn + 4];
            #pragma unroll
            for (int i = 0; i < 8; i++)
                #pragma unroll
                for (int j = 0; j < 8; j++)
                    acc[i][j] += a[i] * bb[j];
        }
    }

    #pragma unroll
    for (int i = 0; i < 8; i++) {
        int rrow = bm + tm + i;
        #pragma unroll
        for (int j = 0; j < 8; j++) {
            int col = bn + tn + j;
            float v = acc[i][j] + bias0[col];
            if (relu) v = fmaxf(v, 0.f);
            C[(size_t)rrow * N + col] = v;
        }
    }
}

// ---------------- final small FC ----------------
__global__ __launch_bounds__(256) void fc_out(
    const float* __restrict__ W, const float* __restrict__ bias, float* __restrict__ out)
{
    int b = blockIdx.x;
    int tid = threadIdx.x;
    const float* trow = g_t + (size_t)b * HDIM;
    float acc[10];
    #pragma unroll
    for (int j = 0; j < 10; j++) acc[j] = 0.f;
    for (int k = tid; k < HDIM; k += 256) {
        float tv = trow[k];
        #pragma unroll
        for (int j = 0; j < 10; j++) acc[j] += tv * W[j * HDIM + k];
    }
    #pragma unroll
    for (int j = 0; j < 10; j++)
        #pragma unroll
        for (int o = 16; o > 0; o >>= 1)
            acc[j] += __shfl_down_sync(0xffffffffu, acc[j], o);
    __shared__ float red[8][10];
    int warp = tid >> 5, lane = tid & 31;
    if (lane == 0)
        #pragma unroll
        for (int j = 0; j < 10; j++) red[warp][j] = acc[j];
    __syncthreads();
    if (tid < 10) {
        float s = bias[tid];
        #pragma unroll
        for (int w = 0; w < 8; w++) s += red[w][tid];
        out[b * 10 + tid] = s;
    }
}

// ---------------- launcher ----------------
extern "C" void kernel_launch(void* const* d_in, const int* in_sizes, int n_in,
                              void* d_out, int out_size)
{
    const float* x      = (const float*)d_in[0];
    const float* W_att  = (const float*)d_in[1];
    const float* b_att  = (const float*)d_in[2];
    const float* W_ih   = (const float*)d_in[3];
    const float* W_hh   = (const float*)d_in[4];
    const float* b_ih   = (const float*)d_in[5];
    const float* b_hh   = (const float*)d_in[6];
    const float* W_fc0  = (const float*)d_in[7];
    const float* b_fc0  = (const float*)d_in[8];
    const float* W_fc   = (const float*)d_in[9];
    const float* b_fc   = (const float*)d_in[10];
    float* out = (float*)d_out;

    void *p_h, *p_t;
    cudaGetSymbolAddress(&p_h, g_h);
    cudaGetSymbolAddress(&p_t, g_t);
    float* s_h = (float*)p_h;
    float* s_t = (float*)p_t;

    cudaFuncSetAttribute(gemm_gates, cudaFuncAttributeMaxDynamicSharedMemorySize, GSMEM);

    convert_weights<<<GATES, 256>>>(W_ih, W_hh, b_ih, b_hh);
    zero_state<<<(BATCH * HDIM) / 256, 256>>>();

    for (int t = 0; t < 16; t++) {
        att_filterbank<<<BATCH, 256>>>(W_att, b_att);
        glimpse_kernel<<<dim3(3, BATCH), 256>>>(x);
        gemm_gates<<<dim3(GATES / 128, BATCH / 128), 256, GSMEM>>>();
        lstm_update<<<(BATCH * HDIM) / 256, 256>>>();
    }

    gemm_bias<<<dim3(HDIM / 128, BATCH / 128), 256>>>(s_h, W_fc0, HDIM, b_fc0, s_t, HDIM, 1);
    fc_out<<<BATCH, 256>>>(W_fc, b_fc, out);
}

// round 5
// speedup vs baseline: 2.1606x; 1.4092x over previous
#include <cuda_runtime.h>
#include <cuda_bf16.h>
#include <math.h>
#include <stdint.h>

#define BATCH 1024
#define HDIM  1024
#define GATES 4096
#define INDIM 768
#define KDIM  1792
#define EPSV  1e-8f

// ---------------- scratch (no allocations allowed) ----------------
__device__ float g_h[BATCH * HDIM];
__device__ float g_c[BATCH * HDIM];
__device__ float g_Fx[BATCH * 1024];
__device__ float g_Fy[BATCH * 1024];
__device__ float g_gamma[BATCH];
__device__ float g_t[BATCH * HDIM];
__device__ float g_biasp[GATES];
__device__ __align__(16) __nv_bfloat16 g_Ah[BATCH * KDIM];
__device__ __align__(16) __nv_bfloat16 g_Al[BATCH * KDIM];
__device__ __align__(16) __nv_bfloat16 g_Wh[(size_t)GATES * KDIM];
__device__ __align__(16) __nv_bfloat16 g_Wl[(size_t)GATES * KDIM];

// ---------------- helpers ----------------
__device__ __forceinline__ uint32_t smem_u32(const void* p) {
    uint32_t a;
    asm("{ .reg .u64 t; cvta.to.shared.u64 t, %1; cvt.u32.u64 %0, t; }" : "=r"(a) : "l"(p));
    return a;
}
static __device__ __forceinline__ void cpa16(uint32_t s, const void* g) {
    asm volatile("cp.async.cg.shared.global [%0], [%1], 16;" :: "r"(s), "l"(g));
}
static __device__ __forceinline__ void ldmx4(uint32_t* r, uint32_t addr) {
    asm volatile("ldmatrix.sync.aligned.m8n8.x4.shared.b16 {%0,%1,%2,%3}, [%4];"
                 : "=r"(r[0]), "=r"(r[1]), "=r"(r[2]), "=r"(r[3]) : "r"(addr));
}
static __device__ __forceinline__ void mma16816(float* d, const uint32_t* a, const uint32_t* b) {
    asm volatile(
        "mma.sync.aligned.m16n8k16.row.col.f32.bf16.bf16.f32 "
        "{%0,%1,%2,%3}, {%4,%5,%6,%7}, {%8,%9}, {%0,%1,%2,%3};"
        : "+f"(d[0]), "+f"(d[1]), "+f"(d[2]), "+f"(d[3])
        : "r"(a[0]), "r"(a[1]), "r"(a[2]), "r"(a[3]), "r"(b[0]), "r"(b[1]));
}
static __device__ __forceinline__ float sigm(float v) { return 1.f / (1.f + __expf(-v)); }
static __device__ __forceinline__ float tanhfast(float v) { return 2.f / (1.f + __expf(-2.f * v)) - 1.f; }

// ---------------- init ----------------
__global__ void zero_state() {
    int idx = blockIdx.x * 256 + threadIdx.x;
    g_h[idx] = 0.f;
    g_c[idx] = 0.f;
    int row = idx >> 10, j = idx & 1023;
    __nv_bfloat16 z = __float2bfloat16(0.f);
    g_Ah[(size_t)row * KDIM + 768 + j] = z;
    g_Al[(size_t)row * KDIM + 768 + j] = z;
}

// ---------------- weight convert: (unit,gate) interleave permutation + bf16 split ----------------
__global__ __launch_bounds__(256) void convert_weights(
    const float* __restrict__ W_ih, const float* __restrict__ W_hh,
    const float* __restrict__ b_ih, const float* __restrict__ b_hh)
{
    int pc = blockIdx.x;                    // permuted row: unit = pc>>2, gate = pc&3
    int orig = (pc & 3) * 1024 + (pc >> 2);
    for (int c = threadIdx.x; c < KDIM; c += 256) {
        float w = (c < 768) ? W_ih[(size_t)orig * 768 + c]
                            : W_hh[(size_t)orig * 1024 + (c - 768)];
        __nv_bfloat16 wh = __float2bfloat16(w);
        g_Wh[(size_t)pc * KDIM + c] = wh;
        g_Wl[(size_t)pc * KDIM + c] = __float2bfloat16(w - __bfloat162float(wh));
    }
    if (threadIdx.x == 0) g_biasp[pc] = b_ih[orig] + b_hh[orig];
}

// ---------------- attention params + filterbank ----------------
__global__ __launch_bounds__(256) void att_filterbank(
    const float* __restrict__ W_att, const float* __restrict__ b_att)
{
    int b = blockIdx.x;
    int tid = threadIdx.x;
    const float* hrow = g_h + (size_t)b * HDIM;

    float a0 = 0.f, a1 = 0.f, a2 = 0.f, a3 = 0.f, a4 = 0.f;
    for (int k = tid; k < HDIM; k += 256) {
        float hv = hrow[k];
        a0 += hv * W_att[k];
        a1 += hv * W_att[HDIM + k];
        a2 += hv * W_att[2 * HDIM + k];
        a3 += hv * W_att[3 * HDIM + k];
        a4 += hv * W_att[4 * HDIM + k];
    }
    #pragma unroll
    for (int o = 16; o > 0; o >>= 1) {
        a0 += __shfl_down_sync(0xffffffffu, a0, o);
        a1 += __shfl_down_sync(0xffffffffu, a1, o);
        a2 += __shfl_down_sync(0xffffffffu, a2, o);
        a3 += __shfl_down_sync(0xffffffffu, a3, o);
        a4 += __shfl_down_sync(0xffffffffu, a4, o);
    }
    __shared__ float red[8][5];
    int warp = tid >> 5, lane = tid & 31;
    if (lane == 0) {
        red[warp][0] = a0; red[warp][1] = a1; red[warp][2] = a2;
        red[warp][3] = a3; red[warp][4] = a4;
    }
    __syncthreads();
    __shared__ float p[5];
    if (tid < 5) {
        float s = b_att[tid];
        #pragma unroll
        for (int w = 0; w < 8; w++) s += red[w][tid];
        p[tid] = s;
    }
    __syncthreads();

    float gx     = 32.5f * (p[0] + 1.f);
    float gy     = 32.5f * (p[1] + 1.f);
    float inv2s2 = 0.5f * expf(-p[2]);
    float delta  = (63.f / 15.f) * expf(p[3]);
    float gam    = expf(p[4]);

    __shared__ float fx[16][65];
    __shared__ float fy[16][65];
    for (int idx = tid; idx < 1024; idx += 256) {
        int i = idx >> 6, a = idx & 63;
        float mu = (i - 8.5f) * delta;
        float dx = (float)a - (gx + mu);
        float dy = (float)a - (gy + mu);
        fx[i][a] = __expf(-dx * dx * inv2s2);
        fy[i][a] = __expf(-dy * dy * inv2s2);
    }
    __syncthreads();
    __shared__ float rs[32];
    if (tid < 32) {
        float s = 0.f;
        if (tid < 16) {
            for (int a = 0; a < 64; a++) s += fx[tid][a];
        } else {
            for (int a = 0; a < 64; a++) s += fy[tid - 16][a];
        }
        rs[tid] = 1.f / (s + EPSV);
    }
    __syncthreads();
    for (int idx = tid; idx < 1024; idx += 256) {
        int i = idx >> 6, a = idx & 63;
        g_Fx[(size_t)b * 1024 + idx] = fx[i][a] * rs[i];
        g_Fy[(size_t)b * 1024 + idx] = fy[i][a] * rs[16 + i];
    }
    if (tid == 0) g_gamma[b] = gam;
}

// ---------------- glimpse: writes split-bf16 r directly into A ----------------
__global__ __launch_bounds__(256) void glimpse_kernel(const float* __restrict__ x)
{
    int c = blockIdx.x;
    int b = blockIdx.y;
    int tid = threadIdx.x;

    __shared__ float simg[64][64];
    __shared__ float sfy[16][64];
    __shared__ float sfx[16][65];
    __shared__ float stmp[16][64];

    const float4* img4 = (const float4*)(x + ((size_t)(b * 3 + c)) * 4096);
    float4* simg4 = (float4*)&simg[0][0];
    for (int i = tid; i < 1024; i += 256) simg4[i] = img4[i];

    const float* fyp = g_Fy + (size_t)b * 1024;
    const float* fxp = g_Fx + (size_t)b * 1024;
    float* sfyf = (float*)sfy;
    for (int i = tid; i < 1024; i += 256) {
        sfyf[i] = fyp[i];
        sfx[i >> 6][i & 63] = fxp[i];
    }
    __syncthreads();

    // phase 1: 4 n-outputs per thread (register tiling)
    {
        int a = tid & 63, ng = tid >> 6;         // ng 0..3
        float ac[4] = {0.f, 0.f, 0.f, 0.f};
        #pragma unroll 8
        for (int y = 0; y < 64; y++) {
            float iv = simg[y][a];
            #pragma unroll
            for (int q = 0; q < 4; q++) ac[q] += sfy[ng * 4 + q][y] * iv;
        }
        #pragma unroll
        for (int q = 0; q < 4; q++) stmp[ng * 4 + q][a] = ac[q];
    }
    __syncthreads();

    // phase 2
    float gam = g_gamma[b];
    int n = tid >> 4, xx = tid & 15;
    float s = 0.f;
    #pragma unroll 8
    for (int a = 0; a < 64; a++) s += stmp[n][a] * sfx[xx][a];
    float v = s * gam;
    __nv_bfloat16 vh = __float2bfloat16(v);
    size_t off = (size_t)b * KDIM + c * 256 + tid;
    g_Ah[off] = vh;
    g_Al[off] = __float2bfloat16(v - __bfloat162float(vh));
}

// ---------------- gates GEMM (mma.sync split-bf16) + fused LSTM epilogue ----------------
// C[1024,4096(perm)] = A[1024,1792] @ W^T; CTA tile 128x256, warp tile 64x64 (2x4 warps),
// BK=32, 3-stage cp.async pipeline. Epilogue applies LSTM and writes h/c/Ah/Al.
#define TA 10240                 // A tile: 128 rows * 80B
#define TB 20480                 // B tile: 256 rows * 80B
#define STG (2 * TA + 2 * TB)    // 61440
#define NSTG 3
#define GSMEM (NSTG * STG + 1024)
#define NKB 56

__global__ __launch_bounds__(256, 1) void gemm_gates()
{
    extern __shared__ char smem[];
    const int tid = threadIdx.x;
    const int lane = tid & 31;
    const int wid = tid >> 5;
    const int wm = wid >> 2;          // 0..1
    const int wn = wid & 3;           // 0..3
    const int bn = blockIdx.x * 256;
    const int bm = blockIdx.y * 128;
    const int ub = bn >> 2;           // unit base (64 units per CTA)

    float* bias_s = (float*)(smem + NSTG * STG);
    for (int i = tid; i < 256; i += 256) bias_s[i] = g_biasp[bn + i];

    float acc[4][8][4];
    #pragma unroll
    for (int i = 0; i < 4; i++)
        #pragma unroll
        for (int j = 0; j < 8; j++)
            #pragma unroll
            for (int q = 0; q < 4; q++) acc[i][j][q] = 0.f;

    const uint32_t a_off = (uint32_t)((wm * 64 + (lane & 15)) * 80 + (lane >> 4) * 16);
    const uint32_t b_row = (uint32_t)(wn * 64 + (lane & 7) + ((lane >> 4) << 3));
    const uint32_t b_off = b_row * 80 + (((uint32_t)lane >> 3) & 1) * 16;

    auto issue = [&](int kb, char* buf) {
        int kcol = kb * 32;
        uint32_t bu = smem_u32(buf);
        #pragma unroll
        for (int i = 0; i < 12; i++) {
            int cid = tid + i * 256;
            const __nv_bfloat16* gp;
            uint32_t so;
            if (cid < 1024) {
                int t = cid >> 9;               // 0=AH 1=AL
                int w = cid & 511;
                int row = w >> 2, ch = w & 3;
                gp = (t ? g_Al : g_Ah) + (size_t)(bm + row) * KDIM + kcol + ch * 8;
                so = t * TA + row * 80 + ch * 16;
            } else {
                int cid2 = cid - 1024;
                int t = cid2 >> 10;             // 0=BH 1=BL
                int w = cid2 & 1023;
                int row = w >> 2, ch = w & 3;
                gp = (t ? g_Wl : g_Wh) + (size_t)(bn + row) * KDIM + kcol + ch * 8;
                so = 2 * TA + t * TB + row * 80 + ch * 16;
            }
            cpa16(bu + so, gp);
        }
    };

    issue(0, smem + 0 * STG);
    asm volatile("cp.async.commit_group;" ::: "memory");
    issue(1, smem + 1 * STG);
    asm volatile("cp.async.commit_group;" ::: "memory");

    int s_cur = 0, s_nxt = 2;
    for (int kb = 0; kb < NKB; kb++) {
        if (kb + 2 < NKB) issue(kb + 2, smem + s_nxt * STG);
        asm volatile("cp.async.commit_group;" ::: "memory");
        asm volatile("cp.async.wait_group 2;" ::: "memory");
        __syncthreads();

        uint32_t sb = smem_u32(smem + s_cur * STG);
        #pragma unroll
        for (int kh = 0; kh < 2; kh++) {
            uint32_t kadd = kh * 32;
            uint32_t aH[4][4], aL[4][4], bH[4][4], bL[4][4];
            #pragma unroll
            for (int mt = 0; mt < 4; mt++)
                ldmx4(aH[mt], sb + a_off + mt * (16 * 80) + kadd);
            #pragma unroll
            for (int g = 0; g < 4; g++)
                ldmx4(bH[g], sb + 2 * TA + b_off + g * (16 * 80) + kadd);

            #pragma unroll
            for (int mt = 0; mt < 4; mt++)
                #pragma unroll
                for (int nt = 0; nt < 8; nt++)
                    mma16816(acc[mt][nt], aH[mt], &bH[nt >> 1][(nt & 1) * 2]);

            #pragma unroll
            for (int g = 0; g < 4; g++)
                ldmx4(bL[g], sb + 2 * TA + TB + b_off + g * (16 * 80) + kadd);
            #pragma unroll
            for (int mt = 0; mt < 4; mt++)
                #pragma unroll
                for (int nt = 0; nt < 8; nt++)
                    mma16816(acc[mt][nt], aH[mt], &bL[nt >> 1][(nt & 1) * 2]);

            #pragma unroll
            for (int mt = 0; mt < 4; mt++)
                ldmx4(aL[mt], sb + TA + a_off + mt * (16 * 80) + kadd);
            #pragma unroll
            for (int mt = 0; mt < 4; mt++)
                #pragma unroll
                for (int nt = 0; nt < 8; nt++)
                    mma16816(acc[mt][nt], aL[mt], &bH[nt >> 1][(nt & 1) * 2]);
        }
        __syncthreads();
        s_cur = (s_cur == 2) ? 0 : s_cur + 1;
        s_nxt = (s_nxt == 2) ? 0 : s_nxt + 1;
    }

    // ---------- fused LSTM epilogue (smem-staged for coalescing) ----------
    float* c_s = (float*)smem;                 // [128][65]
    float* h_s = (float*)(smem + 33536);       // [128][65]

    // load old c coalesced
    for (int i = tid; i < 8192; i += 256) {
        int row = i >> 6, u = i & 63;
        c_s[row * 65 + u] = g_c[(size_t)(bm + row) * HDIM + ub + u];
    }
    __syncthreads();

    #pragma unroll
    for (int mt = 0; mt < 4; mt++) {
        #pragma unroll
        for (int nt = 0; nt < 8; nt++) {
            int colbase = wn * 64 + nt * 8 + (lane & 3) * 2;
            float b0 = bias_s[colbase], b1 = bias_s[colbase + 1];
            #pragma unroll
            for (int half = 0; half < 2; half++) {
                float v0 = acc[mt][nt][half * 2 + 0] + b0;
                float v1 = acc[mt][nt][half * 2 + 1] + b1;
                float p0 = __shfl_xor_sync(0xffffffffu, v0, 1);
                float p1 = __shfl_xor_sync(0xffffffffu, v1, 1);
                if (!(lane & 1)) {
                    // v0=i, v1=f, p0=g, p1=o
                    int rowl = wm * 64 + mt * 16 + (lane >> 2) + half * 8;
                    int uc = (colbase >> 2);   // local unit 0..63
                    float ig = sigm(v0);
                    float fg = sigm(v1);
                    float gg = tanhfast(p0);
                    float og = sigm(p1);
                    float cn = fg * c_s[rowl * 65 + uc] + ig * gg;
                    c_s[rowl * 65 + uc] = cn;
                    h_s[rowl * 65 + uc] = og * tanhfast(cn);
                }
            }
        }
    }
    __syncthreads();

    // write out coalesced: c, h, Ah, Al
    for (int i = tid; i < 8192; i += 256) {
        int row = i >> 6, u = i & 63;
        float cn = c_s[row * 65 + u];
        float hn = h_s[row * 65 + u];
        size_t ro = (size_t)(bm + row);
        g_c[ro * HDIM + ub + u] = cn;
        g_h[ro * HDIM + ub + u] = hn;
        __nv_bfloat16 hh = __float2bfloat16(hn);
        g_Ah[ro * KDIM + 768 + ub + u] = hh;
        g_Al[ro * KDIM + 768 + ub + u] = __float2bfloat16(hn - __bfloat162float(hh));
    }
}

// ---------------- fp32 SGEMM for fc0 ----------------
__global__ __launch_bounds__(256) void gemm_bias(
    const float* __restrict__ A0, const float* __restrict__ W0, int K0,
    const float* __restrict__ bias0, float* __restrict__ C, int N, int relu)
{
    __shared__ float As[2][8][128];
    __shared__ float Bs[2][8][128];

    int tid = threadIdx.x;
    int bm = blockIdx.y * 128;
    int bn = blockIdx.x * 128;
    int lr = tid >> 1;
    int lc = (tid & 1) << 2;
    int nT = K0 >> 3;

    float4 av, bv;
    av = *(const float4*)(A0 + (size_t)(bm + lr) * K0 + lc);
    bv = *(const float4*)(W0 + (size_t)(bn + lr) * K0 + lc);

    float acc[8][8];
    #pragma unroll
    for (int i = 0; i < 8; i++)
        #pragma unroll
        for (int j = 0; j < 8; j++) acc[i][j] = 0.f;

    int tm = (tid >> 4) << 3;
    int tn = (tid & 15) << 3;

    for (int kt = 0; kt < nT; kt++) {
        int buf = kt & 1;
        As[buf][lc + 0][lr] = av.x; As[buf][lc + 1][lr] = av.y;
        As[buf][lc + 2][lr] = av.z; As[buf][lc + 3][lr] = av.w;
        Bs[buf][lc + 0][lr] = bv.x; Bs[buf][lc + 1][lr] = bv.y;
        Bs[buf][lc + 2][lr] = bv.z; Bs[buf][lc + 3][lr] = bv.w;
        __syncthreads();

        if (kt + 1 < nT) {
            int kg = (kt + 1) << 3;
            av = *(const float4*)(A0 + (size_t)(bm + lr) * K0 + kg + lc);
            bv = *(const float4*)(W0 + (size_t)(bn + lr) * K0 + kg + lc);
        }

        #pragma unroll
        for (int k = 0; k < 8; k++) {
            float a[8], bb[8];
            *(float4*)&a[0]  = *(float4*)&As[buf][k][tm];
            *(float4*)&a[4]  = *(float4*)&As[buf][k][tm + 4];
            *(float4*)&bb[0] = *(float4*)&Bs[buf][k][tn];
            *(float4*)&bb[4] = *(float4*)&Bs[buf][k][tn + 4];
            #pragma unroll
            for (int i = 0; i < 8; i++)
                #pragma unroll
                for (int j = 0; j < 8; j++)
                    acc[i][j] += a[i] * bb[j];
        }
    }

    #pragma unroll
    for (int i = 0; i < 8; i++) {
        int rrow = bm + tm + i;
        #pragma unroll
        for (int j = 0; j < 8; j++) {
            int col = bn + tn + j;
            float v = acc[i][j] + bias0[col];
            if (relu) v = fmaxf(v, 0.f);
            C[(size_t)rrow * N + col] = v;
        }
    }
}

// ---------------- final small FC ----------------
__global__ __launch_bounds__(256) void fc_out(
    const float* __restrict__ W, const float* __restrict__ bias, float* __restrict__ out)
{
    int b = blockIdx.x;
    int tid = threadIdx.x;
    const float* trow = g_t + (size_t)b * HDIM;
    float acc[10];
    #pragma unroll
    for (int j = 0; j < 10; j++) acc[j] = 0.f;
    for (int k = tid; k < HDIM; k += 256) {
        float tv = trow[k];
        #pragma unroll
        for (int j = 0; j < 10; j++) acc[j] += tv * W[j * HDIM + k];
    }
    #pragma unroll
    for (int j = 0; j < 10; j++)
        #pragma unroll
        for (int o = 16; o > 0; o >>= 1)
            acc[j] += __shfl_down_sync(0xffffffffu, acc[j], o);
    __shared__ float red[8][10];
    int warp = tid >> 5, lane = tid & 31;
    if (lane == 0)
        #pragma unroll
        for (int j = 0; j < 10; j++) red[warp][j] = acc[j];
    __syncthreads();
    if (tid < 10) {
        float s = bias[tid];
        #pragma unroll
        for (int w = 0; w < 8; w++) s += red[w][tid];
        out[b * 10 + tid] = s;
    }
}

// ---------------- launcher ----------------
extern "C" void kernel_launch(void* const* d_in, const int* in_sizes, int n_in,
                              void* d_out, int out_size)
{
    const float* x      = (const float*)d_in[0];
    const float* W_att  = (const float*)d_in[1];
    const float* b_att  = (const float*)d_in[2];
    const float* W_ih   = (const float*)d_in[3];
    const float* W_hh   = (const float*)d_in[4];
    const float* b_ih   = (const float*)d_in[5];
    const float* b_hh   = (const float*)d_in[6];
    const float* W_fc0  = (const float*)d_in[7];
    const float* b_fc0  = (const float*)d_in[8];
    const float* W_fc   = (const float*)d_in[9];
    const float* b_fc   = (const float*)d_in[10];
    float* out = (float*)d_out;

    void *p_h, *p_t;
    cudaGetSymbolAddress(&p_h, g_h);
    cudaGetSymbolAddress(&p_t, g_t);
    float* s_h = (float*)p_h;
    float* s_t = (float*)p_t;

    cudaFuncSetAttribute(gemm_gates, cudaFuncAttributeMaxDynamicSharedMemorySize, GSMEM);

    convert_weights<<<GATES, 256>>>(W_ih, W_hh, b_ih, b_hh);
    zero_state<<<(BATCH * HDIM) / 256, 256>>>();

    for (int t = 0; t < 16; t++) {
        att_filterbank<<<BATCH, 256>>>(W_att, b_att);
        glimpse_kernel<<<dim3(3, BATCH), 256>>>(x);
        gemm_gates<<<dim3(GATES / 256, BATCH / 128), 256, GSMEM>>>();
    }

    gemm_bias<<<dim3(HDIM / 128, BATCH / 128), 256>>>(s_h, W_fc0, HDIM, b_fc0, s_t, HDIM, 1);
    fc_out<<<BATCH, 256>>>(W_fc, b_fc, out);
}